// round 5
// baseline (speedup 1.0000x reference)
#include <cuda_runtime.h>
#include <cuda_bf16.h>

// GraphAttentionLayer: out = elu(softmax(h_j @ a_j + const) @ h_j)
// SINGLE kernel: online-softmax partial per block, then the LAST block to
// finish (completion counter) combines all partials L2-hot and writes out.
// h_i . a_i is a constant logit shift -> cancels in softmax -> skipped.

#define D        128
#define NB       296          // blocks (2 * 148 SMs -> balanced 2-wave)
#define NT       512          // threads per block
#define WPB      (NT / 32)    // 16 warps
#define NW       (NB * WPB)
#define GRP      (NT / D)     // 4 finalize groups over the dim axis

// Scratch (allocation-free rule -> __device__ globals; zero-initialized)
__device__ float g_m[NB];
__device__ float g_s[NB];
__device__ float g_acc[NB * D];
__device__ unsigned int g_count;

__device__ __forceinline__ float dot4(const float4& h, const float4& a) {
    return h.x * a.x + h.y * a.y + h.z * a.z + h.w * a.w;
}

__device__ __forceinline__ void online_update(float d, const float4& h,
                                              float& m, float& s, float4& acc) {
    float mn = fmaxf(m, d);
    float c  = __expf(m - mn);
    float w  = __expf(d - mn);
    s     = s * c + w;
    acc.x = acc.x * c + w * h.x;
    acc.y = acc.y * c + w * h.y;
    acc.z = acc.z * c + w * h.z;
    acc.w = acc.w * c + w * h.w;
    m = mn;
}

__global__ __launch_bounds__(NT)
void gat_fused(const float* __restrict__ hj, const float* __restrict__ a,
               int nrows, float* __restrict__ out) {
    const int warp = threadIdx.x >> 5;
    const int lane = threadIdx.x & 31;

    // a_j slice for this lane's 4 dims (a_j = a[128:256])
    const float4 aj = *reinterpret_cast<const float4*>(a + D + lane * 4);

    const int gw    = blockIdx.x * WPB + warp;
    const int chunk = (nrows + NW - 1) / NW;
    int r0 = gw * chunk;
    int r1 = r0 + chunk;
    if (r0 > nrows) r0 = nrows;
    if (r1 > nrows) r1 = nrows;
    const int n = (r1 > r0) ? (r1 - r0) : 0;

    float  m = -1e30f;          // finite "neg-inf": no inf-inf NaN on empty warps
    float  s = 0.0f;
    float4 acc = make_float4(0.f, 0.f, 0.f, 0.f);

    const float* base = hj + (size_t)r0 * D + lane * 4;

    int i = 0;
    // 4 rows/iter -> 4 independent 512B warp loads in flight
    for (; i + 4 <= n; i += 4) {
        const float* p = base + (size_t)i * D;
        float4 h0 = *reinterpret_cast<const float4*>(p);
        float4 h1 = *reinterpret_cast<const float4*>(p + D);
        float4 h2 = *reinterpret_cast<const float4*>(p + 2 * D);
        float4 h3 = *reinterpret_cast<const float4*>(p + 3 * D);

        float d0 = dot4(h0, aj);
        float d1 = dot4(h1, aj);
        float d2 = dot4(h2, aj);
        float d3 = dot4(h3, aj);

        #pragma unroll
        for (int o = 16; o > 0; o >>= 1) {
            d0 += __shfl_xor_sync(0xffffffffu, d0, o);
            d1 += __shfl_xor_sync(0xffffffffu, d1, o);
            d2 += __shfl_xor_sync(0xffffffffu, d2, o);
            d3 += __shfl_xor_sync(0xffffffffu, d3, o);
        }

        online_update(d0, h0, m, s, acc);
        online_update(d1, h1, m, s, acc);
        online_update(d2, h2, m, s, acc);
        online_update(d3, h3, m, s, acc);
    }
    for (; i < n; ++i) {
        const float* p = base + (size_t)i * D;
        float4 h = *reinterpret_cast<const float4*>(p);
        float d = dot4(h, aj);
        #pragma unroll
        for (int o = 16; o > 0; o >>= 1)
            d += __shfl_xor_sync(0xffffffffu, d, o);
        online_update(d, h, m, s, acc);
    }

    // ---- Block combine in shared memory ----
    __shared__ float sm_m[WPB];
    __shared__ float sm_s[WPB];
    __shared__ __align__(16) float sm_acc[WPB][D];

    if (lane == 0) { sm_m[warp] = m; sm_s[warp] = s; }
    *reinterpret_cast<float4*>(&sm_acc[warp][lane * 4]) = acc;
    __syncthreads();

    if (threadIdx.x < D) {
        const int d = threadIdx.x;
        float M = -1e30f;
        #pragma unroll
        for (int w = 0; w < WPB; ++w) M = fmaxf(M, sm_m[w]);

        float st = 0.f, ad = 0.f;
        #pragma unroll
        for (int w = 0; w < WPB; ++w) {
            float c = __expf(sm_m[w] - M);
            st += sm_s[w] * c;
            ad += sm_acc[w][d] * c;
        }
        g_acc[blockIdx.x * D + d] = ad;
        if (d == 0) { g_m[blockIdx.x] = M; g_s[blockIdx.x] = st; }
    }

    // ---- Last-block-done finalize (partials still L2-hot) ----
    __threadfence();                       // publish partials before arrival
    __shared__ bool isLast;
    if (threadIdx.x == 0) {
        unsigned v = atomicAdd(&g_count, 1u);
        isLast = (v == NB - 1);
    }
    __syncthreads();
    if (!isLast) return;
    if (threadIdx.x == 0) g_count = 0;     // reset for graph replay

    const int t = threadIdx.x;
    __shared__ float red[WPB];
    __shared__ float sm_M, sm_S;
    __shared__ float sm_c[NB];
    __shared__ __align__(16) float sm_part[GRP][D];

    // global max over g_m (__ldcg: others' writes live at L2, skip stale L1)
    float mreg = (t < NB) ? __ldcg(&g_m[t]) : -1e30f;
    float mv = mreg;
    #pragma unroll
    for (int o = 16; o > 0; o >>= 1) mv = fmaxf(mv, __shfl_xor_sync(0xffffffffu, mv, o));
    if (lane == 0) red[warp] = mv;
    __syncthreads();
    if (t == 0) {
        float v = red[0];
        #pragma unroll
        for (int w = 1; w < WPB; ++w) v = fmaxf(v, red[w]);
        sm_M = v;
    }
    __syncthreads();
    const float M = sm_M;

    // c_b = exp(m_b - M); S = sum s_b * c_b
    float sv = 0.f;
    if (t < NB) {
        float c = __expf(mreg - M);
        sm_c[t] = c;
        sv = __ldcg(&g_s[t]) * c;
    }
    #pragma unroll
    for (int o = 16; o > 0; o >>= 1) sv += __shfl_xor_sync(0xffffffffu, sv, o);
    __syncthreads();                       // sm_c ready; reuse red[]
    if (lane == 0) red[warp] = sv;
    __syncthreads();
    if (t == 0) {
        float v = 0.f;
        #pragma unroll
        for (int w = 0; w < WPB; ++w) v += red[w];
        sm_S = v;
    }
    __syncthreads();

    // combine acc: group g handles blocks b = g, g+GRP, ... (coalesced reads)
    const int d   = t & (D - 1);
    const int grp = t >> 7;
    float ad = 0.f;
    for (int b = grp; b < NB; b += GRP)
        ad += __ldcg(&g_acc[b * D + d]) * sm_c[b];
    sm_part[grp][d] = ad;
    __syncthreads();

    if (t < D) {
        float total = 0.f;
        #pragma unroll
        for (int g = 0; g < GRP; ++g) total += sm_part[g][t];
        float h = total / sm_S;
        out[t] = (h > 0.f) ? h : expm1f(h);   // ELU, alpha = 1
    }
}

extern "C" void kernel_launch(void* const* d_in, const int* in_sizes, int n_in,
                              void* d_out, int out_size) {
    // inputs: [0] h_i (unused: constant logit shift cancels in softmax),
    //         [1] h_j [200000,128] f32, [2] a [256,1] f32
    const float* hj = (const float*)d_in[1];
    const float* a  = (const float*)d_in[2];
    const int nrows = in_sizes[1] / D;

    gat_fused<<<NB, NT>>>(hj, a, nrows, (float*)d_out);
}

// round 6
// speedup vs baseline: 1.1745x; 1.1745x over previous
#include <cuda_runtime.h>
#include <cuda_bf16.h>

// GraphAttentionLayer: out = elu(softmax(h_j @ a_j + const) @ h_j)
// SINGLE kernel, software-pipelined: prefetch next 4 rows while processing
// current 4 (keeps 2KB/warp in flight -> covers DRAM latency at 50% occ).
// Rare-rescale online softmax: warp-uniform branch, common path 1 exp + FMAs.
// Last-block-done finalize combines partials L2-hot.
// h_i . a_i is a constant logit shift -> cancels in softmax -> skipped.

#define D        128
#define NB       296          // blocks (2 * 148 SMs -> balanced 2-wave)
#define NT       512          // threads per block
#define WPB      (NT / 32)    // 16 warps
#define NW       (NB * WPB)
#define GRP      (NT / D)     // 4 finalize groups over the dim axis

__device__ float g_m[NB];
__device__ float g_s[NB];
__device__ float g_acc[NB * D];
__device__ unsigned int g_count;

__device__ __forceinline__ float dot4(const float4& h, const float4& a) {
    return h.x * a.x + h.y * a.y + h.z * a.z + h.w * a.w;
}

// d is warp-uniform. Rescale only when a new max appears (rare).
__device__ __forceinline__ void upd(float d, const float4& h,
                                    float& m, float& s, float4& acc) {
    if (d > m) {                       // warp-uniform, ~4 times per warp total
        float c = __expf(m - d);
        s = s * c + 1.0f;
        acc.x = acc.x * c + h.x;
        acc.y = acc.y * c + h.y;
        acc.z = acc.z * c + h.z;
        acc.w = acc.w * c + h.w;
        m = d;
    } else {                           // common path: 1 MUFU + 5 FMA, m unchanged
        float w = __expf(d - m);
        s += w;
        acc.x += w * h.x;
        acc.y += w * h.y;
        acc.z += w * h.z;
        acc.w += w * h.w;
    }
}

__device__ __forceinline__ void reduce4(float& d0, float& d1, float& d2, float& d3) {
    #pragma unroll
    for (int o = 16; o > 0; o >>= 1) {
        d0 += __shfl_xor_sync(0xffffffffu, d0, o);
        d1 += __shfl_xor_sync(0xffffffffu, d1, o);
        d2 += __shfl_xor_sync(0xffffffffu, d2, o);
        d3 += __shfl_xor_sync(0xffffffffu, d3, o);
    }
}

__global__ __launch_bounds__(NT)
void gat_fused(const float* __restrict__ hj, const float* __restrict__ a,
               int nrows, float* __restrict__ out) {
    const int warp = threadIdx.x >> 5;
    const int lane = threadIdx.x & 31;

    const float4 aj = *reinterpret_cast<const float4*>(a + D + lane * 4);

    const int gw    = blockIdx.x * WPB + warp;
    const int chunk = (nrows + NW - 1) / NW;
    int r0 = gw * chunk;
    int r1 = r0 + chunk;
    if (r0 > nrows) r0 = nrows;
    if (r1 > nrows) r1 = nrows;
    const int n = (r1 > r0) ? (r1 - r0) : 0;

    float  m = -1e30f;
    float  s = 0.0f;
    float4 acc = make_float4(0.f, 0.f, 0.f, 0.f);

    const float* base = hj + (size_t)r0 * D + lane * 4;

    float4 b0, b1, b2, b3;             // prefetch buffer (next 4 rows)
    if (n >= 4) {
        b0 = *reinterpret_cast<const float4*>(base);
        b1 = *reinterpret_cast<const float4*>(base + D);
        b2 = *reinterpret_cast<const float4*>(base + 2 * D);
        b3 = *reinterpret_cast<const float4*>(base + 3 * D);
    }

    int i = 0;
    for (; i + 8 <= n; i += 4) {
        // consume current quad
        float4 h0 = b0, h1 = b1, h2 = b2, h3 = b3;
        // issue next quad's loads NOW (resolve during compute below)
        const float* p = base + (size_t)(i + 4) * D;
        b0 = *reinterpret_cast<const float4*>(p);
        b1 = *reinterpret_cast<const float4*>(p + D);
        b2 = *reinterpret_cast<const float4*>(p + 2 * D);
        b3 = *reinterpret_cast<const float4*>(p + 3 * D);

        float d0 = dot4(h0, aj);
        float d1 = dot4(h1, aj);
        float d2 = dot4(h2, aj);
        float d3 = dot4(h3, aj);
        reduce4(d0, d1, d2, d3);

        upd(d0, h0, m, s, acc);
        upd(d1, h1, m, s, acc);
        upd(d2, h2, m, s, acc);
        upd(d3, h3, m, s, acc);
    }
    if (i + 4 <= n) {                  // last full (prefetched) quad
        float d0 = dot4(b0, aj);
        float d1 = dot4(b1, aj);
        float d2 = dot4(b2, aj);
        float d3 = dot4(b3, aj);
        reduce4(d0, d1, d2, d3);
        upd(d0, b0, m, s, acc);
        upd(d1, b1, m, s, acc);
        upd(d2, b2, m, s, acc);
        upd(d3, b3, m, s, acc);
        i += 4;
    }
    for (; i < n; ++i) {               // scalar tail (< 4 rows)
        const float* p = base + (size_t)i * D;
        float4 h = *reinterpret_cast<const float4*>(p);
        float d = dot4(h, aj);
        #pragma unroll
        for (int o = 16; o > 0; o >>= 1)
            d += __shfl_xor_sync(0xffffffffu, d, o);
        upd(d, h, m, s, acc);
    }

    // ---- Block combine in shared memory ----
    __shared__ float sm_m[WPB];
    __shared__ float sm_s[WPB];
    __shared__ __align__(16) float sm_acc[WPB][D];

    if (lane == 0) { sm_m[warp] = m; sm_s[warp] = s; }
    *reinterpret_cast<float4*>(&sm_acc[warp][lane * 4]) = acc;
    __syncthreads();

    if (threadIdx.x < D) {
        const int d = threadIdx.x;
        float M = -1e30f;
        #pragma unroll
        for (int w = 0; w < WPB; ++w) M = fmaxf(M, sm_m[w]);

        float st = 0.f, ad = 0.f;
        #pragma unroll
        for (int w = 0; w < WPB; ++w) {
            float c = __expf(sm_m[w] - M);
            st += sm_s[w] * c;
            ad += sm_acc[w][d] * c;
        }
        g_acc[blockIdx.x * D + d] = ad;
        if (d == 0) { g_m[blockIdx.x] = M; g_s[blockIdx.x] = st; }
    }

    // ---- Last-block-done finalize (partials L2-hot) ----
    __threadfence();
    __shared__ bool isLast;
    if (threadIdx.x == 0) {
        unsigned v = atomicAdd(&g_count, 1u);
        isLast = (v == NB - 1);
    }
    __syncthreads();
    if (!isLast) return;
    if (threadIdx.x == 0) g_count = 0;     // reset for graph replay

    const int t = threadIdx.x;
    __shared__ float red[WPB];
    __shared__ float sm_M, sm_S;
    __shared__ float sm_c[NB];
    __shared__ __align__(16) float sm_part[GRP][D];

    float mreg = (t < NB) ? __ldcg(&g_m[t]) : -1e30f;
    float mv = mreg;
    #pragma unroll
    for (int o = 16; o > 0; o >>= 1) mv = fmaxf(mv, __shfl_xor_sync(0xffffffffu, mv, o));
    if (lane == 0) red[warp] = mv;
    __syncthreads();
    if (t == 0) {
        float v = red[0];
        #pragma unroll
        for (int w = 1; w < WPB; ++w) v = fmaxf(v, red[w]);
        sm_M = v;
    }
    __syncthreads();
    const float M = sm_M;

    float sv = 0.f;
    if (t < NB) {
        float c = __expf(mreg - M);
        sm_c[t] = c;
        sv = __ldcg(&g_s[t]) * c;
    }
    #pragma unroll
    for (int o = 16; o > 0; o >>= 1) sv += __shfl_xor_sync(0xffffffffu, sv, o);
    __syncthreads();
    if (lane == 0) red[warp] = sv;
    __syncthreads();
    if (t == 0) {
        float v = 0.f;
        #pragma unroll
        for (int w = 0; w < WPB; ++w) v += red[w];
        sm_S = v;
    }
    __syncthreads();

    const int d   = t & (D - 1);
    const int grp = t >> 7;
    float ad = 0.f;
    for (int b = grp; b < NB; b += GRP)
        ad += __ldcg(&g_acc[b * D + d]) * sm_c[b];
    sm_part[grp][d] = ad;
    __syncthreads();

    if (t < D) {
        float total = 0.f;
        #pragma unroll
        for (int g = 0; g < GRP; ++g) total += sm_part[g][t];
        float h = total / sm_S;
        out[t] = (h > 0.f) ? h : expm1f(h);   // ELU, alpha = 1
    }
}

extern "C" void kernel_launch(void* const* d_in, const int* in_sizes, int n_in,
                              void* d_out, int out_size) {
    // inputs: [0] h_i (unused: constant logit shift cancels in softmax),
    //         [1] h_j [200000,128] f32, [2] a [256,1] f32
    const float* hj = (const float*)d_in[1];
    const float* a  = (const float*)d_in[2];
    const int nrows = in_sizes[1] / D;

    gat_fused<<<NB, NT>>>(hj, a, nrows, (float*)d_out);
}